// round 1
// baseline (speedup 1.0000x reference)
#include <cuda_runtime.h>
#include <cuda_bf16.h>
#include <cstdint>

// Problem dims
#define BATCH 256
#define NCOLS 256
#define CH    512
#define NHEAD 8
#define DHEAD 64
#define MROWS (BATCH * NCOLS)   // 65536

// -------- scratch (device globals; allocation is forbidden) --------
__device__ float g_Q[(size_t)MROWS * CH];
__device__ float g_K[(size_t)MROWS * CH];
__device__ float g_V[(size_t)MROWS * CH];
__device__ float g_A[(size_t)MROWS * CH];

// ================= SGEMM with bias: C = A[M,K] @ W[K,N] + b =================
// BM=128, BN=128, BK=8, TM=8, TN=8, 256 threads.
#define BM 128
#define BN 128
#define BK 8
#define TM 8
#define TN 8

__global__ __launch_bounds__(256) void sgemm_bias(
    const float* __restrict__ A, const float* __restrict__ W,
    const float* __restrict__ bias, float* __restrict__ C,
    int M, int N, int K)
{
    const int cRow = blockIdx.y;
    const int cCol = blockIdx.x;

    __shared__ float As[BK * BM];
    __shared__ float Bs[BK * BN];

    A += (size_t)cRow * BM * K;
    W += cCol * BN;
    C += (size_t)cRow * BM * N + cCol * BN;
    bias += cCol * BN;

    const int tid = threadIdx.x;
    const int innerRowA = tid >> 1;          // 0..127
    const int innerColA = (tid & 1) << 2;    // 0 or 4
    const int innerRowB = tid >> 5;          // 0..7
    const int innerColB = (tid & 31) << 2;   // 0..124

    const int threadRow = tid >> 4;          // 0..15
    const int threadCol = tid & 15;          // 0..15

    float acc[TM * TN] = {0.0f};
    float regM[TM], regN[TN];

    for (int k0 = 0; k0 < K; k0 += BK) {
        // load A tile (transpose into smem)
        float4 a = *reinterpret_cast<const float4*>(&A[(size_t)innerRowA * K + innerColA]);
        As[(innerColA + 0) * BM + innerRowA] = a.x;
        As[(innerColA + 1) * BM + innerRowA] = a.y;
        As[(innerColA + 2) * BM + innerRowA] = a.z;
        As[(innerColA + 3) * BM + innerRowA] = a.w;
        // load B tile
        *reinterpret_cast<float4*>(&Bs[innerRowB * BN + innerColB]) =
            *reinterpret_cast<const float4*>(&W[(size_t)innerRowB * N + innerColB]);
        __syncthreads();

        A += BK;
        W += (size_t)BK * N;

        #pragma unroll
        for (int k = 0; k < BK; k++) {
            #pragma unroll
            for (int i = 0; i < TM; i++) regM[i] = As[k * BM + threadRow * TM + i];
            #pragma unroll
            for (int j = 0; j < TN; j++) regN[j] = Bs[k * BN + threadCol * TN + j];
            #pragma unroll
            for (int i = 0; i < TM; i++)
                #pragma unroll
                for (int j = 0; j < TN; j++)
                    acc[i * TN + j] += regM[i] * regN[j];
        }
        __syncthreads();
    }

    // epilogue: bias + vectorized store
    #pragma unroll
    for (int i = 0; i < TM; i++) {
        #pragma unroll
        for (int j4 = 0; j4 < TN; j4 += 4) {
            float4 r;
            r.x = acc[i * TN + j4 + 0] + bias[threadCol * TN + j4 + 0];
            r.y = acc[i * TN + j4 + 1] + bias[threadCol * TN + j4 + 1];
            r.z = acc[i * TN + j4 + 2] + bias[threadCol * TN + j4 + 2];
            r.w = acc[i * TN + j4 + 3] + bias[threadCol * TN + j4 + 3];
            *reinterpret_cast<float4*>(
                &C[(size_t)(threadRow * TM + i) * N + threadCol * TN + j4]) = r;
        }
    }
}

// ================= Fused causal attention per (b, h) =================
// One CTA per (batch, head). K/V head slice staged in smem (2 * 64KB).
// One query per thread; causal loop k<=q. Softmax without max-subtraction:
// allowed scores are ~O(1) after *0.125 scaling; masked entries in the
// reference get (s - 100000)/8 -> exp underflows to exactly 0, so skipping
// k>q is bit-equivalent in effect.
__global__ __launch_bounds__(256) void attn_kernel(
    const float* __restrict__ Q, const float* __restrict__ K,
    const float* __restrict__ V, float* __restrict__ O)
{
    extern __shared__ float smem[];
    float* sK = smem;               // [256][64]
    float* sV = smem + NCOLS * DHEAD;

    const int bx = blockIdx.x;
    const int b = bx >> 3;
    const int h = bx & 7;
    const int tid = threadIdx.x;

    const size_t headOff = (size_t)b * NCOLS * CH + (size_t)h * DHEAD;
    const float* Kbase = K + headOff;
    const float* Vbase = V + headOff;

    // stage K, V (each thread: 16 float4 per tensor, coalesced)
    for (int i = tid; i < NCOLS * (DHEAD / 4); i += 256) {
        const int row = i >> 4;
        const int col = (i & 15) << 2;
        *reinterpret_cast<float4*>(&sK[row * DHEAD + col]) =
            *reinterpret_cast<const float4*>(&Kbase[(size_t)row * CH + col]);
        *reinterpret_cast<float4*>(&sV[row * DHEAD + col]) =
            *reinterpret_cast<const float4*>(&Vbase[(size_t)row * CH + col]);
    }
    __syncthreads();

    const int q = tid;
    const float* Qrow = Q + headOff + (size_t)q * CH;
    float4 qreg[16];
    #pragma unroll
    for (int j = 0; j < 16; j++)
        qreg[j] = reinterpret_cast<const float4*>(Qrow)[j];

    float4 acc[16];
    #pragma unroll
    for (int j = 0; j < 16; j++) acc[j] = make_float4(0.f, 0.f, 0.f, 0.f);
    float l = 0.0f;

    for (int k = 0; k <= q; k++) {
        const float4* Krow = reinterpret_cast<const float4*>(&sK[k * DHEAD]);
        float s0 = 0.f, s1 = 0.f, s2 = 0.f, s3 = 0.f;
        #pragma unroll
        for (int j = 0; j < 16; j += 4) {
            float4 k0 = Krow[j + 0], k1 = Krow[j + 1], k2 = Krow[j + 2], k3 = Krow[j + 3];
            s0 += qreg[j + 0].x * k0.x + qreg[j + 0].y * k0.y + qreg[j + 0].z * k0.z + qreg[j + 0].w * k0.w;
            s1 += qreg[j + 1].x * k1.x + qreg[j + 1].y * k1.y + qreg[j + 1].z * k1.z + qreg[j + 1].w * k1.w;
            s2 += qreg[j + 2].x * k2.x + qreg[j + 2].y * k2.y + qreg[j + 2].z * k2.z + qreg[j + 2].w * k2.w;
            s3 += qreg[j + 3].x * k3.x + qreg[j + 3].y * k3.y + qreg[j + 3].z * k3.z + qreg[j + 3].w * k3.w;
        }
        const float s = ((s0 + s1) + (s2 + s3)) * 0.125f;
        const float p = __expf(s);
        l += p;
        const float4* Vrow = reinterpret_cast<const float4*>(&sV[k * DHEAD]);
        #pragma unroll
        for (int j = 0; j < 16; j++) {
            float4 v = Vrow[j];
            acc[j].x += p * v.x;
            acc[j].y += p * v.y;
            acc[j].z += p * v.z;
            acc[j].w += p * v.w;
        }
    }

    const float inv = 1.0f / l;
    float* Orow = O + headOff + (size_t)q * CH;
    #pragma unroll
    for (int j = 0; j < 16; j++) {
        float4 r = acc[j];
        r.x *= inv; r.y *= inv; r.z *= inv; r.w *= inv;
        reinterpret_cast<float4*>(Orow)[j] = r;
    }
}

// ================= launch =================
extern "C" void kernel_launch(void* const* d_in, const int* in_sizes, int n_in,
                              void* d_out, int out_size)
{
    const float* x  = (const float*)d_in[0];
    const float* Wq = (const float*)d_in[1];
    const float* bq = (const float*)d_in[2];
    const float* Wk = (const float*)d_in[3];
    const float* bk = (const float*)d_in[4];
    const float* Wv = (const float*)d_in[5];
    const float* bv = (const float*)d_in[6];
    const float* Wo = (const float*)d_in[7];
    const float* bo = (const float*)d_in[8];
    float* out = (float*)d_out;

    float *pQ, *pK, *pV, *pA;
    cudaGetSymbolAddress((void**)&pQ, g_Q);
    cudaGetSymbolAddress((void**)&pK, g_K);
    cudaGetSymbolAddress((void**)&pV, g_V);
    cudaGetSymbolAddress((void**)&pA, g_A);

    const int smemAttn = 2 * NCOLS * DHEAD * sizeof(float); // 128 KB
    cudaFuncSetAttribute(attn_kernel, cudaFuncAttributeMaxDynamicSharedMemorySize, smemAttn);

    dim3 gridG(CH / BN, MROWS / BM);  // (4, 512)
    dim3 blockG(256);

    sgemm_bias<<<gridG, blockG>>>(x, Wq, bq, pQ, MROWS, CH, CH);
    sgemm_bias<<<gridG, blockG>>>(x, Wk, bk, pK, MROWS, CH, CH);
    sgemm_bias<<<gridG, blockG>>>(x, Wv, bv, pV, MROWS, CH, CH);

    attn_kernel<<<BATCH * NHEAD, 256, smemAttn>>>(pQ, pK, pV, pA);

    sgemm_bias<<<gridG, blockG>>>(pA, Wo, bo, out, MROWS, CH, CH);
}

// round 4
// speedup vs baseline: 2.2803x; 2.2803x over previous
#include <cuda_runtime.h>
#include <cstdint>

// Problem dims
#define BATCH 256
#define NCOLS 256
#define CH    512
#define NHEAD 8
#define DHEAD 64
#define MROWS (BATCH * NCOLS)   // 65536

// -------- scratch (device globals; allocation is forbidden) --------
__device__ float g_Q[(size_t)MROWS * CH];
__device__ float g_K[(size_t)MROWS * CH];
__device__ float g_V[(size_t)MROWS * CH];
__device__ float g_A[(size_t)MROWS * CH];
__device__ float g_Wt[(size_t)3 * CH * CH];   // transposed Wq|Wk|Wv  [1536 x 512]
__device__ float g_WtO[(size_t)CH * CH];      // transposed Wo        [512 x 512]

// ===================== PTX helpers =====================
__device__ __forceinline__ uint32_t smem_u32(const void* p) {
    uint32_t a;
    asm("{ .reg .u64 t; cvta.to.shared.u64 t, %1; cvt.u32.u64 %0, t; }" : "=r"(a) : "l"(p));
    return a;
}
__device__ __forceinline__ uint32_t tf32r(float x) {   // round-to-nearest tf32
    uint32_t r;
    asm("cvt.rna.tf32.f32 %0, %1;" : "=r"(r) : "f"(x));
    return r;
}
__device__ __forceinline__ void sts128(uint32_t addr, uint32_t a, uint32_t b, uint32_t c, uint32_t d) {
    asm volatile("st.shared.v4.b32 [%0], {%1,%2,%3,%4};" :: "r"(addr), "r"(a), "r"(b), "r"(c), "r"(d) : "memory");
}
#define LDSM4(r, addr)                                                              \
    asm volatile("ldmatrix.sync.aligned.m8n8.x4.shared.b16 {%0,%1,%2,%3}, [%4];"    \
        : "=r"((r)[0]), "=r"((r)[1]), "=r"((r)[2]), "=r"((r)[3]) : "r"(addr))

#define MMA_TF32(d, a, bb0, bb1)                                                    \
    asm volatile("mma.sync.aligned.m16n8k8.row.col.f32.tf32.tf32.f32 "              \
        "{%0,%1,%2,%3}, {%4,%5,%6,%7}, {%8,%9}, {%0,%1,%2,%3};"                     \
        : "+f"((d)[0]), "+f"((d)[1]), "+f"((d)[2]), "+f"((d)[3])                    \
        : "r"((a)[0]), "r"((a)[1]), "r"((a)[2]), "r"((a)[3]), "r"(bb0), "r"(bb1))

// ===================== weight transpose + tf32 round =====================
// Wt[n][k] = round_tf32(W[k][n]),  512x512
__global__ void transpose_round512(const float* __restrict__ W, float* __restrict__ Wt) {
    __shared__ float t[32][33];
    const int bx = blockIdx.x * 32, by = blockIdx.y * 32;
    const int tx = threadIdx.x, ty = threadIdx.y;
    #pragma unroll
    for (int j = 0; j < 32; j += 8)
        t[ty + j][tx] = W[(size_t)(by + ty + j) * CH + bx + tx];
    __syncthreads();
    #pragma unroll
    for (int j = 0; j < 32; j += 8)
        Wt[(size_t)(bx + ty + j) * CH + by + tx] = __uint_as_float(tf32r(t[tx][ty + j]));
}

// ===================== tf32 mma.sync GEMM =====================
// C[128,128] tile per CTA.  C = A[M,512] @ Wt^T + bias.  Wt is [N,512] K-major.
// 4 warps, each 64x64.  K-loop in steps of 16, double-buffered smem.
// smem tile layout: row-major [128 rows][16 cols], 16B units swizzled:
//   unit' = cq ^ ((row>>1)&3)  (verified conflict-free for STS.128 + ldmatrix)
#define NKSTEP 32   // 512 / 16

__global__ __launch_bounds__(128) void gemm_tf32(
    const float* __restrict__ A, const float* __restrict__ Wt,
    const float* __restrict__ b0, const float* __restrict__ b1, const float* __restrict__ b2,
    float* __restrict__ o0, float* __restrict__ o1, float* __restrict__ o2)
{
    __shared__ __align__(1024) uint32_t sA[2][2048];   // 2 x 8KB
    __shared__ __align__(1024) uint32_t sB[2][2048];

    const int tid = threadIdx.x;
    const int lane = tid & 31;
    const int wid = tid >> 5;
    const int warpM = wid >> 1;      // 0..1
    const int warpN = wid & 1;       // 0..1

    const int mat = blockIdx.x >> 2;
    const int colbase = (blockIdx.x & 3) * 128;
    const float* bias = (mat == 0) ? b0 : (mat == 1) ? b1 : b2;
    float* outp = (mat == 0) ? o0 : (mat == 1) ? o1 : o2;

    const uint32_t sAb = smem_u32(sA);
    const uint32_t sBb = smem_u32(sB);

    // ---- staging mapping: thread t loads rows r0+32u, float4 col cq ----
    const int r0 = tid >> 2;        // 0..31
    const int cq = tid & 3;
    const uint32_t swz = (uint32_t)((cq ^ ((r0 >> 1) & 3)) << 4);

    const float* Ag = A + ((size_t)blockIdx.y * 128 + r0) * CH + cq * 4;
    const float* Bg = Wt + ((size_t)blockIdx.x * 128 + r0) * CH + cq * 4;

    // ---- ldmatrix per-lane addressing ----
    const int l3 = lane & 7;
    const int a_tb = (lane >> 3) & 1, a_cb = (lane >> 4) & 1;
    const int b_tb = (lane >> 4) & 1, b_cb = (lane >> 3) & 1;
    const int key = (l3 >> 1) & 3;
    const uint32_t aRowOff = (uint32_t)((warpM * 64 + a_tb * 8 + l3) * 64);
    const uint32_t bRowOff = (uint32_t)((warpN * 64 + b_tb * 8 + l3) * 64);
    uint32_t aCu[2], bCu[2];
    #pragma unroll
    for (int k8 = 0; k8 < 2; k8++) {
        aCu[k8] = (uint32_t)((((k8 << 1) | a_cb) ^ key) << 4);
        bCu[k8] = (uint32_t)((((k8 << 1) | b_cb) ^ key) << 4);
    }

    float acc[4][8][4];
    #pragma unroll
    for (int i = 0; i < 4; i++)
        #pragma unroll
        for (int j = 0; j < 8; j++)
            #pragma unroll
            for (int k = 0; k < 4; k++) acc[i][j][k] = 0.0f;

    // prologue: load tile 0
    float4 va[4], vb[4];
    #pragma unroll
    for (int u = 0; u < 4; u++) {
        va[u] = *(const float4*)(Ag + (size_t)u * 32 * CH);
        vb[u] = *(const float4*)(Bg + (size_t)u * 32 * CH);
    }

    #pragma unroll 1
    for (int s = 0; s < NKSTEP; s++) {
        const int d = s & 1;
        const uint32_t dA = sAb + d * 8192;
        const uint32_t dB = sBb + d * 8192;
        __syncthreads();
        #pragma unroll
        for (int u = 0; u < 4; u++) {
            const uint32_t ro = (uint32_t)((r0 + 32 * u) * 64) + swz;
            sts128(dA + ro, tf32r(va[u].x), tf32r(va[u].y), tf32r(va[u].z), tf32r(va[u].w));
            sts128(dB + ro, tf32r(vb[u].x), tf32r(vb[u].y), tf32r(vb[u].z), tf32r(vb[u].w));
        }
        __syncthreads();

        if (s + 1 < NKSTEP) {
            const int ko = (s + 1) * 16;
            #pragma unroll
            for (int u = 0; u < 4; u++) {
                va[u] = *(const float4*)(Ag + ko + (size_t)u * 32 * CH);
                vb[u] = *(const float4*)(Bg + ko + (size_t)u * 32 * CH);
            }
        }

        #pragma unroll
        for (int k8 = 0; k8 < 2; k8++) {
            uint32_t aF[4][4], bF[4][4];
            #pragma unroll
            for (int mt = 0; mt < 4; mt++)
                LDSM4(aF[mt], dA + aRowOff + (uint32_t)(mt * 16 * 64) + aCu[k8]);
            #pragma unroll
            for (int p = 0; p < 4; p++)
                LDSM4(bF[p], dB + bRowOff + (uint32_t)(p * 16 * 64) + bCu[k8]);
            #pragma unroll
            for (int mt = 0; mt < 4; mt++)
                #pragma unroll
                for (int nt = 0; nt < 8; nt++) {
                    const int p = nt >> 1;
                    if (nt & 1) { MMA_TF32(acc[mt][nt], aF[mt], bF[p][2], bF[p][3]); }
                    else        { MMA_TF32(acc[mt][nt], aF[mt], bF[p][0], bF[p][1]); }
                }
        }
    }

    // ---- epilogue ----
    const int gid = lane >> 2, tig = lane & 3;
    #pragma unroll
    for (int mt = 0; mt < 4; mt++) {
        const int row0 = blockIdx.y * 128 + warpM * 64 + mt * 16 + gid;
        #pragma unroll
        for (int nt = 0; nt < 8; nt++) {
            const int col = colbase + warpN * 64 + nt * 8 + tig * 2;
            const float bv0 = __ldg(&bias[col]);
            const float bv1 = __ldg(&bias[col + 1]);
            float2 v0 = make_float2(acc[mt][nt][0] + bv0, acc[mt][nt][1] + bv1);
            float2 v1 = make_float2(acc[mt][nt][2] + bv0, acc[mt][nt][3] + bv1);
            *(float2*)(outp + (size_t)row0 * CH + col) = v0;
            *(float2*)(outp + (size_t)(row0 + 8) * CH + col) = v1;
        }
    }
}

// ===================== Fused causal attention per (b, h) =====================
__global__ __launch_bounds__(256) void attn_kernel(
    const float* __restrict__ Q, const float* __restrict__ K,
    const float* __restrict__ V, float* __restrict__ O)
{
    extern __shared__ float smemf[];
    float* sK = smemf;               // [256][64]
    float* sV = smemf + NCOLS * DHEAD;

    const int bx = blockIdx.x;
    const int b = bx >> 3;
    const int h = bx & 7;
    const int tid = threadIdx.x;

    const size_t headOff = (size_t)b * NCOLS * CH + (size_t)h * DHEAD;
    const float* Kbase = K + headOff;
    const float* Vbase = V + headOff;

    for (int i = tid; i < NCOLS * (DHEAD / 4); i += 256) {
        const int row = i >> 4;
        const int col = (i & 15) << 2;
        *reinterpret_cast<float4*>(&sK[row * DHEAD + col]) =
            *reinterpret_cast<const float4*>(&Kbase[(size_t)row * CH + col]);
        *reinterpret_cast<float4*>(&sV[row * DHEAD + col]) =
            *reinterpret_cast<const float4*>(&Vbase[(size_t)row * CH + col]);
    }
    __syncthreads();

    const int q = tid;
    const float* Qrow = Q + headOff + (size_t)q * CH;
    float4 qreg[16];
    #pragma unroll
    for (int j = 0; j < 16; j++)
        qreg[j] = reinterpret_cast<const float4*>(Qrow)[j];

    float4 acc[16];
    #pragma unroll
    for (int j = 0; j < 16; j++) acc[j] = make_float4(0.f, 0.f, 0.f, 0.f);
    float l = 0.0f;

    for (int k = 0; k <= q; k++) {
        const float4* Krow = reinterpret_cast<const float4*>(&sK[k * DHEAD]);
        float s0 = 0.f, s1 = 0.f, s2 = 0.f, s3 = 0.f;
        #pragma unroll
        for (int j = 0; j < 16; j += 4) {
            float4 k0 = Krow[j + 0], k1 = Krow[j + 1], k2 = Krow[j + 2], k3 = Krow[j + 3];
            s0 += qreg[j + 0].x * k0.x + qreg[j + 0].y * k0.y + qreg[j + 0].z * k0.z + qreg[j + 0].w * k0.w;
            s1 += qreg[j + 1].x * k1.x + qreg[j + 1].y * k1.y + qreg[j + 1].z * k1.z + qreg[j + 1].w * k1.w;
            s2 += qreg[j + 2].x * k2.x + qreg[j + 2].y * k2.y + qreg[j + 2].z * k2.z + qreg[j + 2].w * k2.w;
            s3 += qreg[j + 3].x * k3.x + qreg[j + 3].y * k3.y + qreg[j + 3].z * k3.z + qreg[j + 3].w * k3.w;
        }
        const float s = ((s0 + s1) + (s2 + s3)) * 0.125f;
        const float p = __expf(s);
        l += p;
        const float4* Vrow = reinterpret_cast<const float4*>(&sV[k * DHEAD]);
        #pragma unroll
        for (int j = 0; j < 16; j++) {
            float4 v = Vrow[j];
            acc[j].x += p * v.x;
            acc[j].y += p * v.y;
            acc[j].z += p * v.z;
            acc[j].w += p * v.w;
        }
    }

    const float inv = 1.0f / l;
    float* Orow = O + headOff + (size_t)q * CH;
    #pragma unroll
    for (int j = 0; j < 16; j++) {
        float4 r = acc[j];
        r.x *= inv; r.y *= inv; r.z *= inv; r.w *= inv;
        reinterpret_cast<float4*>(Orow)[j] = r;
    }
}

// ===================== launch =====================
extern "C" void kernel_launch(void* const* d_in, const int* in_sizes, int n_in,
                              void* d_out, int out_size)
{
    const float* x  = (const float*)d_in[0];
    const float* Wq = (const float*)d_in[1];
    const float* bq = (const float*)d_in[2];
    const float* Wk = (const float*)d_in[3];
    const float* bk = (const float*)d_in[4];
    const float* Wv = (const float*)d_in[5];
    const float* bv = (const float*)d_in[6];
    const float* Wo = (const float*)d_in[7];
    const float* bo = (const float*)d_in[8];
    float* out = (float*)d_out;

    float *pQ, *pK, *pV, *pA, *pWt, *pWtO;
    cudaGetSymbolAddress((void**)&pQ, g_Q);
    cudaGetSymbolAddress((void**)&pK, g_K);
    cudaGetSymbolAddress((void**)&pV, g_V);
    cudaGetSymbolAddress((void**)&pA, g_A);
    cudaGetSymbolAddress((void**)&pWt, g_Wt);
    cudaGetSymbolAddress((void**)&pWtO, g_WtO);

    const int smemAttn = 2 * NCOLS * DHEAD * sizeof(float); // 128 KB
    cudaFuncSetAttribute(attn_kernel, cudaFuncAttributeMaxDynamicSharedMemorySize, smemAttn);

    dim3 tgrid(16, 16), tblk(32, 8);
    transpose_round512<<<tgrid, tblk>>>(Wq, pWt);
    transpose_round512<<<tgrid, tblk>>>(Wk, pWt + (size_t)CH * CH);
    transpose_round512<<<tgrid, tblk>>>(Wv, pWt + (size_t)2 * CH * CH);
    transpose_round512<<<tgrid, tblk>>>(Wo, pWtO);

    // QKV fused: N-tiles 0..11 -> (Q|K|V) x 4 col-tiles, M-tiles 0..511
    gemm_tf32<<<dim3(12, 512), 128>>>(x, pWt, bq, bk, bv, pQ, pK, pV);

    attn_kernel<<<BATCH * NHEAD, 256, smemAttn>>>(pQ, pK, pV, pA);

    // output projection
    gemm_tf32<<<dim3(4, 512), 128>>>(pA, pWtO, bo, bo, bo, out, out, out);
}

// round 5
// speedup vs baseline: 3.7191x; 1.6310x over previous
#include <cuda_runtime.h>
#include <cstdint>

// Problem dims
#define BATCH 256
#define NCOLS 256
#define CH    512
#define NHEAD 8
#define DHEAD 64
#define MROWS (BATCH * NCOLS)   // 65536

// -------- scratch (device globals; allocation is forbidden) --------
__device__ float g_Q[(size_t)MROWS * CH];
__device__ float g_K[(size_t)MROWS * CH];
__device__ float g_V[(size_t)MROWS * CH];
__device__ float g_A[(size_t)MROWS * CH];
__device__ float g_Wt[(size_t)3 * CH * CH];   // transposed Wq|Wk|Wv  [1536 x 512]
__device__ float g_WtO[(size_t)CH * CH];      // transposed Wo        [512 x 512]

// ===================== PTX helpers =====================
__device__ __forceinline__ uint32_t smem_u32(const void* p) {
    uint32_t a;
    asm("{ .reg .u64 t; cvta.to.shared.u64 t, %1; cvt.u32.u64 %0, t; }" : "=r"(a) : "l"(p));
    return a;
}
__device__ __forceinline__ uint32_t tf32r(float x) {   // round-to-nearest tf32
    uint32_t r;
    asm("cvt.rna.tf32.f32 %0, %1;" : "=r"(r) : "f"(x));
    return r;
}
__device__ __forceinline__ float tf32rf(float x) { return __uint_as_float(tf32r(x)); }
__device__ __forceinline__ void sts128(uint32_t addr, uint32_t a, uint32_t b, uint32_t c, uint32_t d) {
    asm volatile("st.shared.v4.b32 [%0], {%1,%2,%3,%4};" :: "r"(addr), "r"(a), "r"(b), "r"(c), "r"(d) : "memory");
}
__device__ __forceinline__ void sts32(uint32_t addr, uint32_t a) {
    asm volatile("st.shared.b32 [%0], %1;" :: "r"(addr), "r"(a) : "memory");
}
__device__ __forceinline__ void sts64f(uint32_t addr, float a, float b) {
    asm volatile("st.shared.v2.f32 [%0], {%1,%2};" :: "r"(addr), "f"(a), "f"(b) : "memory");
}
#define LDSM4(r, addr)                                                              \
    asm volatile("ldmatrix.sync.aligned.m8n8.x4.shared.b16 {%0,%1,%2,%3}, [%4];"    \
        : "=r"((r)[0]), "=r"((r)[1]), "=r"((r)[2]), "=r"((r)[3]) : "r"(addr))

#define MMA_TF32(d, a, bb0, bb1)                                                    \
    asm volatile("mma.sync.aligned.m16n8k8.row.col.f32.tf32.tf32.f32 "              \
        "{%0,%1,%2,%3}, {%4,%5,%6,%7}, {%8,%9}, {%0,%1,%2,%3};"                     \
        : "+f"((d)[0]), "+f"((d)[1]), "+f"((d)[2]), "+f"((d)[3])                    \
        : "r"((a)[0]), "r"((a)[1]), "r"((a)[2]), "r"((a)[3]), "r"(bb0), "r"(bb1))

// ===================== weight transpose + tf32 round =====================
__global__ void transpose_round512(const float* __restrict__ W, float* __restrict__ Wt) {
    __shared__ float t[32][33];
    const int bx = blockIdx.x * 32, by = blockIdx.y * 32;
    const int tx = threadIdx.x, ty = threadIdx.y;
    #pragma unroll
    for (int j = 0; j < 32; j += 8)
        t[ty + j][tx] = W[(size_t)(by + ty + j) * CH + bx + tx];
    __syncthreads();
    #pragma unroll
    for (int j = 0; j < 32; j += 8)
        Wt[(size_t)(bx + ty + j) * CH + by + tx] = __uint_as_float(tf32r(t[tx][ty + j]));
}

// ===================== tf32 mma.sync GEMM (unchanged from R4) =====================
#define NKSTEP 32   // 512 / 16

__global__ __launch_bounds__(128) void gemm_tf32(
    const float* __restrict__ A, const float* __restrict__ Wt,
    const float* __restrict__ b0, const float* __restrict__ b1, const float* __restrict__ b2,
    float* __restrict__ o0, float* __restrict__ o1, float* __restrict__ o2)
{
    __shared__ __align__(1024) uint32_t sA[2][2048];
    __shared__ __align__(1024) uint32_t sB[2][2048];

    const int tid = threadIdx.x;
    const int lane = tid & 31;
    const int wid = tid >> 5;
    const int warpM = wid >> 1;
    const int warpN = wid & 1;

    const int mat = blockIdx.x >> 2;
    const int colbase = (blockIdx.x & 3) * 128;
    const float* bias = (mat == 0) ? b0 : (mat == 1) ? b1 : b2;
    float* outp = (mat == 0) ? o0 : (mat == 1) ? o1 : o2;

    const uint32_t sAb = smem_u32(sA);
    const uint32_t sBb = smem_u32(sB);

    const int r0 = tid >> 2;
    const int cq = tid & 3;
    const uint32_t swz = (uint32_t)((cq ^ ((r0 >> 1) & 3)) << 4);

    const float* Ag = A + ((size_t)blockIdx.y * 128 + r0) * CH + cq * 4;
    const float* Bg = Wt + ((size_t)blockIdx.x * 128 + r0) * CH + cq * 4;

    const int l3 = lane & 7;
    const int a_tb = (lane >> 3) & 1, a_cb = (lane >> 4) & 1;
    const int b_tb = (lane >> 4) & 1, b_cb = (lane >> 3) & 1;
    const int key = (l3 >> 1) & 3;
    const uint32_t aRowOff = (uint32_t)((warpM * 64 + a_tb * 8 + l3) * 64);
    const uint32_t bRowOff = (uint32_t)((warpN * 64 + b_tb * 8 + l3) * 64);
    uint32_t aCu[2], bCu[2];
    #pragma unroll
    for (int k8 = 0; k8 < 2; k8++) {
        aCu[k8] = (uint32_t)((((k8 << 1) | a_cb) ^ key) << 4);
        bCu[k8] = (uint32_t)((((k8 << 1) | b_cb) ^ key) << 4);
    }

    float acc[4][8][4];
    #pragma unroll
    for (int i = 0; i < 4; i++)
        #pragma unroll
        for (int j = 0; j < 8; j++)
            #pragma unroll
            for (int k = 0; k < 4; k++) acc[i][j][k] = 0.0f;

    float4 va[4], vb[4];
    #pragma unroll
    for (int u = 0; u < 4; u++) {
        va[u] = *(const float4*)(Ag + (size_t)u * 32 * CH);
        vb[u] = *(const float4*)(Bg + (size_t)u * 32 * CH);
    }

    #pragma unroll 1
    for (int s = 0; s < NKSTEP; s++) {
        const int d = s & 1;
        const uint32_t dA = sAb + d * 8192;
        const uint32_t dB = sBb + d * 8192;
        __syncthreads();
        #pragma unroll
        for (int u = 0; u < 4; u++) {
            const uint32_t ro = (uint32_t)((r0 + 32 * u) * 64) + swz;
            sts128(dA + ro, tf32r(va[u].x), tf32r(va[u].y), tf32r(va[u].z), tf32r(va[u].w));
            sts128(dB + ro, tf32r(vb[u].x), tf32r(vb[u].y), tf32r(vb[u].z), tf32r(vb[u].w));
        }
        __syncthreads();

        if (s + 1 < NKSTEP) {
            const int ko = (s + 1) * 16;
            #pragma unroll
            for (int u = 0; u < 4; u++) {
                va[u] = *(const float4*)(Ag + ko + (size_t)u * 32 * CH);
                vb[u] = *(const float4*)(Bg + ko + (size_t)u * 32 * CH);
            }
        }

        #pragma unroll
        for (int k8 = 0; k8 < 2; k8++) {
            uint32_t aF[4][4], bF[4][4];
            #pragma unroll
            for (int mt = 0; mt < 4; mt++)
                LDSM4(aF[mt], dA + aRowOff + (uint32_t)(mt * 16 * 64) + aCu[k8]);
            #pragma unroll
            for (int p = 0; p < 4; p++)
                LDSM4(bF[p], dB + bRowOff + (uint32_t)(p * 16 * 64) + bCu[k8]);
            #pragma unroll
            for (int mt = 0; mt < 4; mt++)
                #pragma unroll
                for (int nt = 0; nt < 8; nt++) {
                    const int p = nt >> 1;
                    if (nt & 1) { MMA_TF32(acc[mt][nt], aF[mt], bF[p][2], bF[p][3]); }
                    else        { MMA_TF32(acc[mt][nt], aF[mt], bF[p][0], bF[p][1]); }
                }
        }
    }

    const int gid = lane >> 2, tig = lane & 3;
    #pragma unroll
    for (int mt = 0; mt < 4; mt++) {
        const int row0 = blockIdx.y * 128 + warpM * 64 + mt * 16 + gid;
        #pragma unroll
        for (int nt = 0; nt < 8; nt++) {
            const int col = colbase + warpN * 64 + nt * 8 + tig * 2;
            const float bv0 = __ldg(&bias[col]);
            const float bv1 = __ldg(&bias[col + 1]);
            float2 v0 = make_float2(acc[mt][nt][0] + bv0, acc[mt][nt][1] + bv1);
            float2 v1 = make_float2(acc[mt][nt][2] + bv0, acc[mt][nt][3] + bv1);
            *(float2*)(outp + (size_t)row0 * CH + col) = v0;
            *(float2*)(outp + (size_t)(row0 + 8) * CH + col) = v1;
        }
    }
}

// ===================== tensor-core causal attention =====================
// One CTA per (b,h). 8 warps; warp w handles 16-row query strips {w, 15-w}
// => exactly 17 key-blocks of 16 per warp (balanced causal).
// smem: sQ[256][64] (64KB) | sK[256][64] (64KB) | sVt[64][256] (64KB) | sP 8x1KB.
// Q/K rows: 16 units of 16B, phys unit = (L&8)|((L&7)^(row&7)).
// Vt rows: 64 units, phys = (L&~7)|((L&7)^(row&7)).
// P (per warp, 16x16): 4 units/row, phys = L ^ ((row>>1)&3).
#define ATT_SMEM (196608 + 8192)

__global__ __launch_bounds__(256, 1) void attn_mma(
    const float* __restrict__ Q, const float* __restrict__ K,
    const float* __restrict__ V, float* __restrict__ O)
{
    extern __shared__ char smem[];
    const uint32_t sb = smem_u32(smem);
    const uint32_t qb = sb;
    const uint32_t kb = sb + 65536;
    const uint32_t vb = sb + 131072;

    const int tid = threadIdx.x;
    const int lane = tid & 31;
    const int wid = tid >> 5;
    const uint32_t pb = sb + 196608 + wid * 1024;

    const int b = blockIdx.x >> 3;
    const int h = blockIdx.x & 7;
    const size_t headOff = (size_t)b * NCOLS * CH + (size_t)h * DHEAD;

    // ---- stage Q, K (tf32, swizzled) ----
    #pragma unroll
    for (int i = 0; i < 16; i++) {
        const int id = tid + 256 * i;
        const int row = id >> 4;
        const int L = id & 15;
        const uint32_t phys = (uint32_t)((L & 8) | ((L & 7) ^ (row & 7)));
        const uint32_t off = (uint32_t)(row * 256) + phys * 16;
        float4 q = *(const float4*)(Q + headOff + (size_t)row * CH + L * 4);
        sts128(qb + off, tf32r(q.x), tf32r(q.y), tf32r(q.z), tf32r(q.w));
        float4 k = *(const float4*)(K + headOff + (size_t)row * CH + L * 4);
        sts128(kb + off, tf32r(k.x), tf32r(k.y), tf32r(k.z), tf32r(k.w));
    }
    // ---- stage V transposed: Vt[d][key], tf32, swizzled ----
    {
        const int keyr = tid;
        const int Lv = keyr >> 2;
        const uint32_t cbyte = (uint32_t)((keyr & 3) * 4);
        #pragma unroll
        for (int c = 0; c < 16; c++) {
            float4 v = *(const float4*)(V + headOff + (size_t)keyr * CH + c * 4);
            #pragma unroll
            for (int i = 0; i < 4; i++) {
                const int row = 4 * c + i;
                const uint32_t phys = (uint32_t)((Lv & ~7) | ((Lv & 7) ^ (row & 7)));
                const float val = (i == 0) ? v.x : (i == 1) ? v.y : (i == 2) ? v.z : v.w;
                sts32(vb + (uint32_t)(row * 1024) + phys * 16 + cbyte, tf32r(val));
            }
        }
    }
    __syncthreads();

    const int l3 = lane & 7;
    const int a_tb = (lane >> 3) & 1, a_cb = (lane >> 4) & 1;
    const int b_tb = (lane >> 4) & 1, b_cb = (lane >> 3) & 1;
    const int g = lane >> 2, t = lane & 3;
    const int pkey = (l3 >> 1) & 3;

    #pragma unroll 1
    for (int pass = 0; pass < 2; pass++) {
        const int s = pass ? (15 - wid) : wid;

        // Q fragments for this strip
        uint32_t qF[8][4];
        #pragma unroll
        for (int k8 = 0; k8 < 8; k8++) {
            const int L = k8 * 2 + a_cb;
            const uint32_t phys = (uint32_t)((L & 8) | ((L & 7) ^ l3));
            LDSM4(qF[k8], qb + (uint32_t)((s * 16 + a_tb * 8 + l3) * 256) + phys * 16);
        }

        float o[8][4];
        #pragma unroll
        for (int i = 0; i < 8; i++)
            #pragma unroll
            for (int e = 0; e < 4; e++) o[i][e] = 0.0f;
        float l0 = 0.0f, l1 = 0.0f;

        #pragma unroll 1
        for (int j = 0; j <= s; j++) {
            // ---- S = Q Kt ----
            float sc[2][4];
            #pragma unroll
            for (int nt = 0; nt < 2; nt++)
                #pragma unroll
                for (int e = 0; e < 4; e++) sc[nt][e] = 0.0f;
            #pragma unroll
            for (int k8 = 0; k8 < 8; k8++) {
                const int L = k8 * 2 + b_cb;
                const uint32_t phys = (uint32_t)((L & 8) | ((L & 7) ^ l3));
                uint32_t kF[4];
                LDSM4(kF, kb + (uint32_t)((j * 16 + b_tb * 8 + l3) * 256) + phys * 16);
                MMA_TF32(sc[0], qF[k8], kF[0], kF[1]);
                MMA_TF32(sc[1], qF[k8], kF[2], kF[3]);
            }
            // ---- exp + causal mask + tf32 round ----
            float p[2][4];
            const bool diag = (j == s);
            #pragma unroll
            for (int nt = 0; nt < 2; nt++) {
                const int col = nt * 8 + 2 * t;
                #pragma unroll
                for (int e = 0; e < 4; e++) {
                    const int cc = col + (e & 1);
                    const int rr = (e < 2) ? g : (g + 8);
                    const bool keep = !diag || (cc <= rr);
                    p[nt][e] = keep ? tf32rf(__expf(sc[nt][e] * 0.125f)) : 0.0f;
                }
                l0 += p[nt][0] + p[nt][1];
                l1 += p[nt][2] + p[nt][3];
            }
            // ---- store P to per-warp smem ----
            __syncwarp();
            #pragma unroll
            for (int nt = 0; nt < 2; nt++) {
                const int col = nt * 8 + 2 * t;
                const uint32_t u = (uint32_t)(((col >> 2) ^ ((g >> 1) & 3)) << 4) + (uint32_t)((col & 3) * 4);
                sts64f(pb + (uint32_t)(g * 64) + u, p[nt][0], p[nt][1]);
                sts64f(pb + (uint32_t)((g + 8) * 64) + u, p[nt][2], p[nt][3]);
            }
            __syncwarp();
            // ---- O += P V ----
            #pragma unroll
            for (int k8 = 0; k8 < 2; k8++) {
                uint32_t aF[4];
                const uint32_t pu = (uint32_t)((((k8 * 2) + a_cb) ^ pkey) << 4);
                LDSM4(aF, pb + (uint32_t)((a_tb * 8 + l3) * 64) + pu);
                #pragma unroll
                for (int p4 = 0; p4 < 4; p4++) {
                    const int L = j * 4 + k8 * 2 + b_cb;
                    const uint32_t phys = (uint32_t)((L & ~7) | ((L & 7) ^ l3));
                    uint32_t vF[4];
                    LDSM4(vF, vb + (uint32_t)((p4 * 16 + b_tb * 8 + l3) * 1024) + phys * 16);
                    MMA_TF32(o[2 * p4], aF, vF[0], vF[1]);
                    MMA_TF32(o[2 * p4 + 1], aF, vF[2], vF[3]);
                }
            }
        }

        // ---- normalize + write ----
        l0 += __shfl_xor_sync(0xFFFFFFFFu, l0, 1);
        l0 += __shfl_xor_sync(0xFFFFFFFFu, l0, 2);
        l1 += __shfl_xor_sync(0xFFFFFFFFu, l1, 1);
        l1 += __shfl_xor_sync(0xFFFFFFFFu, l1, 2);
        const float inv0 = 1.0f / l0;
        const float inv1 = 1.0f / l1;

        const int row0 = s * 16 + g;
        float* Ob0 = (float*)(O + headOff + (size_t)row0 * CH);
        float* Ob1 = (float*)(O + headOff + (size_t)(row0 + 8) * CH);
        #pragma unroll
        for (int nt = 0; nt < 8; nt++) {
            const int col = nt * 8 + 2 * t;
            *(float2*)(Ob0 + col) = make_float2(o[nt][0] * inv0, o[nt][1] * inv0);
            *(float2*)(Ob1 + col) = make_float2(o[nt][2] * inv1, o[nt][3] * inv1);
        }
    }
}

// ===================== launch =====================
extern "C" void kernel_launch(void* const* d_in, const int* in_sizes, int n_in,
                              void* d_out, int out_size)
{
    const float* x  = (const float*)d_in[0];
    const float* Wq = (const float*)d_in[1];
    const float* bq = (const float*)d_in[2];
    const float* Wk = (const float*)d_in[3];
    const float* bk = (const float*)d_in[4];
    const float* Wv = (const float*)d_in[5];
    const float* bv = (const float*)d_in[6];
    const float* Wo = (const float*)d_in[7];
    const float* bo = (const float*)d_in[8];
    float* out = (float*)d_out;

    float *pQ, *pK, *pV, *pA, *pWt, *pWtO;
    cudaGetSymbolAddress((void**)&pQ, g_Q);
    cudaGetSymbolAddress((void**)&pK, g_K);
    cudaGetSymbolAddress((void**)&pV, g_V);
    cudaGetSymbolAddress((void**)&pA, g_A);
    cudaGetSymbolAddress((void**)&pWt, g_Wt);
    cudaGetSymbolAddress((void**)&pWtO, g_WtO);

    cudaFuncSetAttribute(attn_mma, cudaFuncAttributeMaxDynamicSharedMemorySize, ATT_SMEM);

    dim3 tgrid(16, 16), tblk(32, 8);
    transpose_round512<<<tgrid, tblk>>>(Wq, pWt);
    transpose_round512<<<tgrid, tblk>>>(Wk, pWt + (size_t)CH * CH);
    transpose_round512<<<tgrid, tblk>>>(Wv, pWt + (size_t)2 * CH * CH);
    transpose_round512<<<tgrid, tblk>>>(Wo, pWtO);

    // QKV fused: N-tiles 0..11 -> (Q|K|V) x 4 col-tiles, M-tiles 0..511
    gemm_tf32<<<dim3(12, 512), 128>>>(x, pWt, bq, bk, bv, pQ, pK, pV);

    attn_mma<<<BATCH * NHEAD, 256, ATT_SMEM>>>(pQ, pK, pV, pA);

    // output projection
    gemm_tf32<<<dim3(4, 512), 128>>>(pA, pWtO, bo, bo, bo, out, out, out);
}